// round 16
// baseline (speedup 1.0000x reference)
#include <cuda_runtime.h>
#include <cuda_fp16.h>
#include <cstdint>
#include <cstddef>

#define NB     4
#define NSEQ   4096
#define EDIM   128
#define FFD    512
#define NTOK   (NB * NSEQ)

// ---------------- scratch ----------------
__device__ __half g_hh  [NTOK * EDIM];
__device__ float  g_S   [NTOK * EDIM];
__device__ __half g_Xh  [NTOK * 256];
__device__ __half g_atth[NTOK * EDIM];
__device__ float  g_out1[NTOK * EDIM];
__device__ __half g_h2h [NTOK * EDIM];
__device__ __half g_th  [NTOK * FFD];
__device__ __half g_W1h [EDIM * FFD];
__device__ __half g_W2h [FFD * EDIM];
__device__ __half g_Woh [EDIM * EDIM];
__device__ __half g_Wqh [EDIM * EDIM];
__device__ __half g_Wkh [EDIM * EDIM];
__device__ __half g_Wvh [EDIM * EDIM];

// ---------------- helpers ----------------
__device__ __forceinline__ void mma_f16(float* c, const uint32_t* a, const uint32_t* b) {
    asm volatile(
        "mma.sync.aligned.m16n8k16.row.col.f32.f16.f16.f32 "
        "{%0,%1,%2,%3}, {%4,%5,%6,%7}, {%8,%9}, {%0,%1,%2,%3};\n"
        : "+f"(c[0]), "+f"(c[1]), "+f"(c[2]), "+f"(c[3])
        : "r"(a[0]), "r"(a[1]), "r"(a[2]), "r"(a[3]), "r"(b[0]), "r"(b[1]));
}
__device__ __forceinline__ void cp16(void* s, const void* gp) {
    uint32_t sa = (uint32_t)__cvta_generic_to_shared(s);
    asm volatile("cp.async.cg.shared.global [%0], [%1], 16;\n" :: "r"(sa), "l"(gp));
}
__device__ __forceinline__ void cp_commit() {
    asm volatile("cp.async.commit_group;\n" ::: "memory");
}
__device__ __forceinline__ void cp_wait0() {
    asm volatile("cp.async.wait_group 0;\n" ::: "memory");
}
__device__ __forceinline__ void cp_wait1() {
    asm volatile("cp.async.wait_group 1;\n" ::: "memory");
}
__device__ __forceinline__ void ldmx4(uint32_t& r0, uint32_t& r1, uint32_t& r2,
                                      uint32_t& r3, uint32_t addr) {
    asm volatile("ldmatrix.sync.aligned.m8n8.x4.shared.b16 {%0,%1,%2,%3}, [%4];"
                 : "=r"(r0), "=r"(r1), "=r"(r2), "=r"(r3) : "r"(addr));
}
__device__ __forceinline__ void ldmx4t(uint32_t& r0, uint32_t& r1, uint32_t& r2,
                                       uint32_t& r3, uint32_t addr) {
    asm volatile("ldmatrix.sync.aligned.m8n8.x4.trans.shared.b16 {%0,%1,%2,%3}, [%4];"
                 : "=r"(r0), "=r"(r1), "=r"(r2), "=r"(r3) : "r"(addr));
}
__device__ __forceinline__ uint32_t smem_u32(const void* p) {
    return (uint32_t)__cvta_generic_to_shared(p);
}

// ---------------------------------------------------------------------------
// Prep: blocks [0, 2048): rmsnorm(x) -> g_hh (half);
//       blocks [2048, 2304): pack weights to half
// ---------------------------------------------------------------------------
__global__ void prep_kernel(const float* __restrict__ x,
                            const float* __restrict__ gw,
                            const float* __restrict__ W1,
                            const float* __restrict__ W2,
                            const float* __restrict__ Wo,
                            const float* __restrict__ Wq,
                            const float* __restrict__ Wk,
                            const float* __restrict__ Wv) {
    if (blockIdx.x < 2048) {
        int warp = (blockIdx.x * blockDim.x + threadIdx.x) >> 5;
        int lane = threadIdx.x & 31;
        float4 v = reinterpret_cast<const float4*>(x + (size_t)warp * EDIM)[lane];
        float ss = v.x * v.x + v.y * v.y + v.z * v.z + v.w * v.w;
        #pragma unroll
        for (int o = 16; o > 0; o >>= 1) ss += __shfl_xor_sync(0xffffffffu, ss, o);
        float s = rsqrtf(ss * (1.0f / 128.0f) + 1e-6f);
        float4 g4 = reinterpret_cast<const float4*>(gw)[lane];
        __half2 h0 = __floats2half2_rn(v.x * s * g4.x, v.y * s * g4.y);
        __half2 h1 = __floats2half2_rn(v.z * s * g4.z, v.w * s * g4.w);
        uint2 u;
        u.x = *reinterpret_cast<uint32_t*>(&h0);
        u.y = *reinterpret_cast<uint32_t*>(&h1);
        *reinterpret_cast<uint2*>(g_hh + (size_t)warp * EDIM + lane * 4) = u;
    } else {
        int i = (blockIdx.x - 2048) * blockDim.x + threadIdx.x;
        g_W1h[i] = __float2half(W1[i]);
        g_W2h[i] = __float2half(W2[i]);
        if (i < EDIM * EDIM) {
            g_Woh[i] = __float2half(Wo[i]);
            g_Wqh[i] = __float2half(Wq[i]);
            g_Wkh[i] = __float2half(Wk[i]);
            g_Wvh[i] = __float2half(Wv[i]);
        }
    }
}

// ---------------------------------------------------------------------------
// QKV (fp16, K=128 resident, one sync) — unchanged from R15
// ---------------------------------------------------------------------------
#define Q2_ASTR 136
#define Q2_BOFF 17408
#define Q2_BSTR 40
#define Q2_BBUF 5120
#define QKV_SMEM ((Q2_BOFF + 3 * Q2_BBUF) * 2)

__global__ __launch_bounds__(256)
void qkv_kernel() {
    extern __shared__ __half smq[];
    __half* Ah = smq;
    __half* Bh = smq + Q2_BOFF;
    const uint32_t smb = smem_u32(smq);

    const int m0 = blockIdx.x * 128;
    const int j0 = blockIdx.y * 32;
    const int tid = threadIdx.x, lane = tid & 31, warp = tid >> 5;
    const int wm = warp >> 1, wn = warp & 1;
    const int g = lane >> 2, tg = lane & 3;
    const int lr = lane & 7, sel = lane >> 3;

    const __half* Wh[3] = {g_Wqh, g_Wkh, g_Wvh};

    #pragma unroll
    for (int i = 0; i < 8; i++) {
        int id = tid + i * 256;
        int m = id >> 4, c = (id & 15) << 3;
        cp16(Ah + m * Q2_ASTR + c, g_hh + (size_t)(m0 + m) * 128 + c);
    }
    #pragma unroll
    for (int w = 0; w < 3; w++) {
        #pragma unroll
        for (int i = 0; i < 2; i++) {
            int id = tid + i * 256;
            int k = id >> 2, c = (id & 3) << 3;
            cp16(Bh + w * Q2_BBUF + k * Q2_BSTR + c,
                 Wh[w] + (size_t)k * 128 + j0 + c);
        }
    }
    cp_commit();
    cp_wait0();
    __syncthreads();

    uint32_t aoff[2];
    #pragma unroll
    for (int mt = 0; mt < 2; ++mt)
        aoff[mt] = (uint32_t)((wm * 32 + mt * 16 + (sel & 1) * 8 + lr) * Q2_ASTR +
                              (sel >> 1) * 8);
    const uint32_t lmB = (uint32_t)((lane & 15) * Q2_BSTR + wn * 16 + ((lane >> 4) << 3));

    float acc[3][2][2][4];
    #pragma unroll
    for (int w = 0; w < 3; w++)
        #pragma unroll
        for (int i = 0; i < 2; i++)
            #pragma unroll
            for (int j = 0; j < 2; j++)
                #pragma unroll
                for (int r = 0; r < 4; r++) acc[w][i][j][r] = 0.0f;

    #pragma unroll
    for (int kb = 0; kb < 128; kb += 16) {
        uint32_t a[2][4];
        #pragma unroll
        for (int mt = 0; mt < 2; ++mt)
            ldmx4(a[mt][0], a[mt][1], a[mt][2], a[mt][3],
                  smb + 2u * (aoff[mt] + kb));
        #pragma unroll
        for (int w = 0; w < 3; w++) {
            uint32_t r0, r1, r2, r3;
            ldmx4t(r0, r1, r2, r3,
                   smb + 2u * (Q2_BOFF + w * Q2_BBUF + lmB + kb * Q2_BSTR));
            uint32_t b0[2] = {r0, r1}, b1[2] = {r2, r3};
            mma_f16(acc[w][0][0], a[0], b0);
            mma_f16(acc[w][1][0], a[1], b0);
            mma_f16(acc[w][0][1], a[0], b1);
            mma_f16(acc[w][1][1], a[1], b1);
        }
    }

    #pragma unroll
    for (int mt = 0; mt < 2; ++mt) {
        #pragma unroll
        for (int nt = 0; nt < 2; ++nt) {
            const int col = j0 + wn * 16 + nt * 8 + tg * 2;
            #pragma unroll
            for (int hh = 0; hh < 2; ++hh) {
                const int row = m0 + wm * 32 + mt * 16 + g + hh * 8;
                float q0 = acc[0][mt][nt][hh * 2], q1 = acc[0][mt][nt][hh * 2 + 1];
                float k0v = acc[1][mt][nt][hh * 2], k1v = acc[1][mt][nt][hh * 2 + 1];
                float v0 = acc[2][mt][nt][hh * 2], v1 = acc[2][mt][nt][hh * 2 + 1];
                float2 s2 = make_float2(1.0f / (1.0f + expf(-q0)),
                                        1.0f / (1.0f + expf(-q1)));
                *reinterpret_cast<float2*>(g_S + (size_t)row * 128 + col) = s2;
                float kw0 = expf(k0v), kw1 = expf(k1v);
                __half2 h0 = __floats2half2_rn(kw0 * v0, kw0);
                __half2 h1 = __floats2half2_rn(kw1 * v1, kw1);
                uint2 u;
                u.x = *reinterpret_cast<uint32_t*>(&h0);
                u.y = *reinterpret_cast<uint32_t*>(&h1);
                *reinterpret_cast<uint2*>(g_Xh + (size_t)row * 256 + 2 * col) = u;
            }
        }
    }
}

// ---------------------------------------------------------------------------
// Big GEMM (fp16 m16n8k16). R10 per-thread structure verbatim, but BM=64,
// 256 threads, grid 256 -> 2 CTAs/SM co-residency doubles A-load MLP.
// 8 warps = 2m x 4n, warp tile 32m x 64n. dis traffic unchanged (M-split).
// ---------------------------------------------------------------------------
#define AH_STR 40
#define AH_BUF 2560              // 64*40 halfs
#define BH_STR 264
#define BH_BUF 8448
#define BH_OFF 5120              // after 2 A buffers
#define BIG_SMEM ((BH_OFF + 3 * BH_BUF) * 2)   // 60928 bytes

__global__ __launch_bounds__(256, 2)
void big_kernel(const float* __restrict__ dis, const float* __restrict__ alphap) {
    extern __shared__ __half smh[];
    __half* Ah = smh;
    __half* Bh = smh + BH_OFF;
    const uint32_t smb = smem_u32(smh);

    const int tid = threadIdx.x, lane = tid & 31, warp = tid >> 5;
    const int wm = warp >> 2, wn = warp & 3;     // 2m x 4n
    const int g = lane >> 2, tg = lane & 3;
    const int b = blockIdx.y, j0 = blockIdx.x * 64;
    const float coef = 12.0f * alphap[0];
    const float* Ag = dis + (size_t)b * NSEQ * NSEQ;
    const __half* Xg = g_Xh + (size_t)b * NSEQ * 256;

    const int am = tid & 63, ar4 = (tid >> 6) << 2;   // col m (0..63), 4 k-rows

    const int lr = lane & 7, sel = lane >> 3;
    uint32_t aoff[2];
    #pragma unroll
    for (int mt = 0; mt < 2; ++mt)
        aoff[mt] = (uint32_t)((wm * 32 + mt * 16 + (sel & 1) * 8 + lr) * AH_STR +
                              (sel >> 1) * 8);
    const uint32_t lm_half = (uint32_t)((lane & 15) * BH_STR + wn * 64 + ((lane >> 4) << 3));

    float ra[2][4];
    float acc[2][8][4];
    #pragma unroll
    for (int i = 0; i < 2; i++)
        #pragma unroll
        for (int j = 0; j < 8; j++)
            #pragma unroll
            for (int r = 0; r < 4; r++) acc[i][j][r] = 0.0f;

    auto ldA = [&](int k0) {
        #pragma unroll
        for (int it = 0; it < 2; ++it) {
            const float* p = Ag + (size_t)(k0 + it * 16 + ar4) * NSEQ + j0 + am;
            ra[it][0] = p[0]; ra[it][1] = p[NSEQ];
            ra[it][2] = p[2 * NSEQ]; ra[it][3] = p[3 * NSEQ];
        }
    };
    auto stA = [&](int buf) {
        __half* base = Ah + buf * AH_BUF + am * AH_STR;
        #pragma unroll
        for (int it = 0; it < 2; ++it) {
            __half2 h01 = __floats2half2_rn(__expf(-coef * ra[it][0]),
                                            __expf(-coef * ra[it][1]));
            __half2 h23 = __floats2half2_rn(__expf(-coef * ra[it][2]),
                                            __expf(-coef * ra[it][3]));
            uint2 u;
            u.x = *reinterpret_cast<uint32_t*>(&h01);
            u.y = *reinterpret_cast<uint32_t*>(&h23);
            *reinterpret_cast<uint2*>(base + it * 16 + ar4) = u;
        }
    };
    auto cpB = [&](int stage, int k0) {
        #pragma unroll
        for (int it = 0; it < 4; ++it) {
            int ch = tid + it * 256;
            int row = ch >> 5, cc = (ch & 31) << 3;
            cp16(Bh + stage * BH_BUF + row * BH_STR + cc,
                 Xg + (size_t)(k0 + row) * 256 + cc);
        }
    };

    cpB(0, 0);  cp_commit();
    cpB(1, 32); cp_commit();
    ldA(0);
    stA(0);
    cp_wait1();
    __syncthreads();

    for (int kt = 0; kt < 128; ++kt) {
        const int sbuf = kt % 3;
        const int abuf = kt & 1;
        if (kt + 2 < 128) { cpB((kt + 2) % 3, (kt + 2) * 32); cp_commit(); }
        if (kt + 1 < 128) ldA((kt + 1) * 32);

        const uint32_t abase = smb + 2u * (abuf * AH_BUF);
        const uint32_t bbase = smb + 2u * (BH_OFF + sbuf * BH_BUF + lm_half);
        #pragma unroll
        for (int ks = 0; ks < 2; ++ks) {
            const int kb = ks * 16;
            uint32_t a[2][4];
            #pragma unroll
            for (int mt = 0; mt < 2; ++mt)
                ldmx4(a[mt][0], a[mt][1], a[mt][2], a[mt][3],
                      abase + 2u * (aoff[mt] + kb));
            #pragma unroll
            for (int np = 0; np < 4; ++np) {
                uint32_t r0, r1, r2, r3;
                ldmx4t(r0, r1, r2, r3, bbase + 2u * (kb * BH_STR + np * 16));
                uint32_t b0[2] = {r0, r1}, b1[2] = {r2, r3};
                mma_f16(acc[0][np * 2],     a[0], b0);
                mma_f16(acc[1][np * 2],     a[1], b0);
                mma_f16(acc[0][np * 2 + 1], a[0], b1);
                mma_f16(acc[1][np * 2 + 1], a[1], b1);
            }
        }
        if (kt + 1 < 128) stA(abuf ^ 1);
        cp_wait1();
        __syncthreads();
    }

    const size_t rowbase = (size_t)b * NSEQ + j0;
    #pragma unroll
    for (int mt = 0; mt < 2; ++mt) {
        const int r0 = wm * 32 + mt * 16 + g;
        #pragma unroll
        for (int nt = 0; nt < 8; ++nt) {
            const int e = wn * 32 + nt * 4 + tg;
            const size_t i0 = (rowbase + r0) * 128 + e;
            const size_t i1 = (rowbase + r0 + 8) * 128 + e;
            float a0 = g_S[i0] * __fdividef(acc[mt][nt][0], acc[mt][nt][1]);
            float a1 = g_S[i1] * __fdividef(acc[mt][nt][2], acc[mt][nt][3]);
            g_atth[i0] = __float2half(a0);
            g_atth[i1] = __float2half(a1);
        }
    }
}

// ---------------------------------------------------------------------------
// Wo (fp16 resident) + residual + fused post-rmsnorm. BM=64 — unchanged
// ---------------------------------------------------------------------------
#define WO_STR 136
#define WO_BOFF 8704
#define WO_SMEM ((WO_BOFF + 128 * WO_STR) * 2)

__global__ __launch_bounds__(256)
void wo_norm_kernel(const float* __restrict__ x, const float* __restrict__ gpost,
                    float* __restrict__ out1) {
    extern __shared__ __half smw[];
    __shared__ float rowss[64];
    __half* Ah = smw;
    __half* Bh = smw + WO_BOFF;
    const uint32_t smb = smem_u32(smw);

    const int m0 = blockIdx.x * 64;
    const int tid = threadIdx.x, lane = tid & 31, warp = tid >> 5;
    const int wm = warp >> 2, wn = warp & 3;
    const int g = lane >> 2, tg = lane & 3;
    const int lr = lane & 7, sel = lane >> 3;

    #pragma unroll
    for (int i = 0; i < 4; i++) {
        int id = tid + i * 256;
        int m = id >> 4, c = (id & 15) << 3;
        cp16(Ah + m * WO_STR + c, g_atth + (size_t)(m0 + m) * 128 + c);
    }
    #pragma unroll
    for (int i = 0; i < 8; i++) {
        int id = tid + i * 256;
        int m = id >> 4, c = (id & 15) << 3;
        cp16(Bh + m * WO_STR + c, g_Woh + (size_t)m * 128 + c);
    }
    cp_commit();
    if (tid < 64) rowss[tid] = 0.0f;
    cp_wait0();
    __syncthreads();

    uint32_t aoff[2];
    #pragma unroll
    for (int mt = 0; mt < 2; ++mt)
        aoff[mt] = (uint32_t)((wm * 32 + mt * 16 + (sel & 1) * 8 + lr) * WO_STR +
                              (sel >> 1) * 8);
    const uint32_t lm = (uint32_t)((lane & 15) * WO_STR + wn * 32 + ((lane >> 4) << 3));

    float acc[2][4][4];
    #pragma unroll
    for (int i = 0; i < 2; i++)
        #pragma unroll
        for (int j = 0; j < 4; j++)
            #pragma unroll
            for (int r = 0; r < 4; r++) acc[i][j][r] = 0.0f;

    #pragma unroll
    for (int kb = 0; kb < 128; kb += 16) {
        uint32_t a[2][4];
        #pragma unroll
        for (int mt = 0; mt < 2; ++mt)
            ldmx4(a[mt][0], a[mt][1], a[mt][2], a[mt][3],
                  smb + 2u * (aoff[mt] + kb));
        #pragma unroll
        for (int np = 0; np < 2; ++np) {
            uint32_t r0, r1, r2, r3;
            ldmx4t(r0, r1, r2, r3,
                   smb + 2u * (WO_BOFF + lm + kb * WO_STR + np * 16));
            uint32_t b0[2] = {r0, r1}, b1r[2] = {r2, r3};
            mma_f16(acc[0][np * 2],     a[0], b0);
            mma_f16(acc[1][np * 2],     a[1], b0);
            mma_f16(acc[0][np * 2 + 1], a[0], b1r);
            mma_f16(acc[1][np * 2 + 1], a[1], b1r);
        }
    }

    #pragma unroll
    for (int mt = 0; mt < 2; ++mt) {
        #pragma unroll
        for (int h = 0; h < 2; ++h) {
            const int rl = wm * 32 + mt * 16 + g + h * 8;
            const size_t rowg = (size_t)(m0 + rl);
            float ss = 0.0f;
            #pragma unroll
            for (int nt = 0; nt < 4; ++nt) {
                const int c = wn * 32 + nt * 8 + tg * 2;
                float2 xv = *reinterpret_cast<const float2*>(x + rowg * 128 + c);
                float v0 = acc[mt][nt][h * 2 + 0] + xv.x;
                float v1 = acc[mt][nt][h * 2 + 1] + xv.y;
                acc[mt][nt][h * 2 + 0] = v0;
                acc[mt][nt][h * 2 + 1] = v1;
                *reinterpret_cast<float2*>(out1 + rowg * 128 + c) = make_float2(v0, v1);
                ss += v0 * v0 + v1 * v1;
            }
            ss += __shfl_xor_sync(0xffffffffu, ss, 1);
            ss += __shfl_xor_sync(0xffffffffu, ss, 2);
            if (tg == 0) atomicAdd(&rowss[rl], ss);
        }
    }
    __syncthreads();

    #pragma unroll
    for (int mt = 0; mt < 2; ++mt) {
        #pragma unroll
        for (int h = 0; h < 2; ++h) {
            const int rl = wm * 32 + mt * 16 + g + h * 8;
            const size_t rowg = (size_t)(m0 + rl);
            const float sc = rsqrtf(rowss[rl] * (1.0f / 128.0f) + 1e-6f);
            #pragma unroll
            for (int nt = 0; nt < 4; ++nt) {
                const int c = wn * 32 + nt * 8 + tg * 2;
                float2 gp = *reinterpret_cast<const float2*>(gpost + c);
                __half2 hv = __floats2half2_rn(acc[mt][nt][h * 2 + 0] * sc * gp.x,
                                               acc[mt][nt][h * 2 + 1] * sc * gp.y);
                *reinterpret_cast<uint32_t*>(g_h2h + rowg * 128 + c) =
                    *reinterpret_cast<uint32_t*>(&hv);
            }
        }
    }
}

// ---------------------------------------------------------------------------
// FF1 (fp16 resident) — unchanged
// ---------------------------------------------------------------------------
#define F1_ASTR 136
#define F1_BOFF 17408
#define F1_BSTR 72
#define F1_SMEM ((F1_BOFF + 128 * F1_BSTR) * 2)

__global__ __launch_bounds__(256)
void ff1_kernel(const float* __restrict__ b1) {
    extern __shared__ __half smf[];
    __half* Ah = smf;
    __half* Bh = smf + F1_BOFF;
    const uint32_t smb = smem_u32(smf);

    const int m0 = blockIdx.x * 128;
    const int n0 = blockIdx.y * 64;
    const int tid = threadIdx.x, lane = tid & 31, warp = tid >> 5;
    const int wm = warp >> 1, wn = warp & 1;
    const int g = lane >> 2, tg = lane & 3;
    const int lr = lane & 7, sel = lane >> 3;

    #pragma unroll
    for (int i = 0; i < 8; i++) {
        int id = tid + i * 256;
        int m = id >> 4, c = (id & 15) << 3;
        cp16(Ah + m * F1_ASTR + c, g_h2h + (size_t)(m0 + m) * 128 + c);
    }
    #pragma unroll
    for (int i = 0; i < 4; i++) {
        int id = tid + i * 256;
        int k = id >> 3, c = (id & 7) << 3;
        cp16(Bh + k * F1_BSTR + c, g_W1h + (size_t)k * FFD + n0 + c);
    }
    cp_commit();
    cp_wait0();
    __syncthreads();

    uint32_t aoff[2];
    #pragma unroll
    for (int mt = 0; mt < 2; ++mt)
        aoff[mt] = (uint32_t)((wm * 32 + mt * 16 + (sel & 1) * 8 + lr) * F1_ASTR +
                              (sel >> 1) * 8);
    const uint32_t lm = (uint32_t)((lane & 15) * F1_BSTR + wn * 32 + ((lane >> 4) << 3));

    float acc[2][4][4];
    #pragma unroll
    for (int i = 0; i < 2; i++)
        #pragma unroll
        for (int j = 0; j < 4; j++)
            #pragma unroll
            for (int r = 0; r < 4; r++) acc[i][j][r] = 0.0f;

    #pragma unroll
    for (int kb = 0; kb < 128; kb += 16) {
        uint32_t a[2][4];
        #pragma unroll
        for (int mt = 0; mt < 2; ++mt)
            ldmx4(a[mt][0], a[mt][1], a[mt][2], a[mt][3],
                  smb + 2u * (aoff[mt] + kb));
        #pragma unroll
        for (int np = 0; np < 2; ++np) {
            uint32_t r0, r1, r2, r3;
            ldmx4t(r0, r1, r2, r3,
                   smb + 2u * (F1_BOFF + lm + kb * F1_BSTR + np * 16));
            uint32_t b0[2] = {r0, r1}, b1r[2] = {r2, r3};
            mma_f16(acc[0][np * 2],     a[0], b0);
            mma_f16(acc[1][np * 2],     a[1], b0);
            mma_f16(acc[0][np * 2 + 1], a[0], b1r);
            mma_f16(acc[1][np * 2 + 1], a[1], b1r);
        }
    }

    #pragma unroll
    for (int mt = 0; mt < 2; ++mt) {
        #pragma unroll
        for (int nt = 0; nt < 4; ++nt) {
            const int col = n0 + wn * 32 + nt * 8 + tg * 2;
            const float bb0 = b1[col], bb1 = b1[col + 1];
            #pragma unroll
            for (int h = 0; h < 2; ++h) {
                const int row = m0 + wm * 32 + mt * 16 + g + h * 8;
                float v0 = fmaxf(acc[mt][nt][h * 2 + 0] + bb0, 0.0f);
                float v1 = fmaxf(acc[mt][nt][h * 2 + 1] + bb1, 0.0f);
                __half2 hv = __floats2half2_rn(v0, v1);
                *reinterpret_cast<uint32_t*>(g_th + (size_t)row * FFD + col) =
                    *reinterpret_cast<uint32_t*>(&hv);
            }
        }
    }
}

// ---------------------------------------------------------------------------
// FF2 (fp16): BM=64, BK=64 double-buffered — unchanged
// ---------------------------------------------------------------------------
#define F2_ASTR 72
#define F2_ABUF 4608
#define F2_BSTR 136
#define F2_BBUF 8704
#define F2_STAGE (F2_ABUF + F2_BBUF)
#define F2_SMEM (2 * F2_STAGE * 2)

__global__ __launch_bounds__(256)
void ff2_kernel(const float* __restrict__ b2, const float* __restrict__ res,
                float* __restrict__ out) {
    extern __shared__ __half smf[];
    const uint32_t smb = smem_u32(smf);

    const int m0 = blockIdx.x * 64;
    const int tid = threadIdx.x, lane = tid & 31, warp = tid >> 5;
    const int wm = warp >> 2, wn = warp & 3;
    const int g = lane >> 2, tg = lane & 3;
    const int lr = lane & 7, sel = lane >> 3;

    auto cpTile = [&](int stage, int k0) {
        __half* As = smf + stage * F2_STAGE;
        __half* Bs = As + F2_ABUF;
        #pragma unroll
        for (int i = 0; i < 2; i++) {
            int id = tid + i * 256;
            int m = id >> 3, c = (id & 7) << 3;
            cp16(As + m * F2_ASTR + c, g_th + (size_t)(m0 + m) * FFD + k0 + c);
        }
        #pragma unroll
        for (int i = 0; i < 4; i++) {
            int id = tid + i * 256;
            int k = id >> 4, c = (id & 15) << 3;
            cp16(Bs + k * F2_BSTR + c, g_W2h + (size_t)(k0 + k) * EDIM + c);
        }
    };

    uint32_t aoff[2];
    #pragma unroll
    for (int mt = 0; mt < 2; ++mt)
        aoff[mt] = (uint32_t)((wm * 32 + mt * 16 + (sel & 1) * 8 + lr) * F2_ASTR +
                              (sel >> 1) * 8);
    const uint32_t lm = (uint32_t)((lane & 15) * F2_BSTR + wn * 32 + ((lane >> 4) << 3));

    float acc[2][4][4];
    #pragma unroll
    for (int i = 0; i < 2; i++)
        #pragma unroll
        for (int j = 0; j < 4; j++)
            #pragma unroll
            for (int r = 0; r < 4; r++) acc[i][j][r] = 0.0f;

    cpTile(0, 0);
    cp_commit();

    for (int kt = 0; kt < 8; ++kt) {
        const int stage = kt & 1;
        if (kt + 1 < 8) { cpTile(stage ^ 1, (kt + 1) * 64); cp_commit(); cp_wait1(); }
        else            { cp_wait0(); }
        __syncthreads();
        const uint32_t abase = smb + 2u * (stage * F2_STAGE);
        const uint32_t bbase = smb + 2u * (stage * F2_STAGE + F2_ABUF + lm);
        #pragma unroll
        for (int ks = 0; ks < 4; ++ks) {
            const int kb = ks * 16;
            uint32_t a[2][4];
            #pragma unroll
            for (int mt = 0; mt < 2; ++mt)
                ldmx4(a[mt][0], a[mt][1], a[mt][2], a[mt][3],
                      abase + 2u * (aoff[mt] + kb));
            #pragma unroll
            for (int np = 0; np < 2; ++np) {
                uint32_t r0, r1, r2, r3;
                ldmx4t(r0, r1, r2, r3, bbase + 2u * (kb * F2_BSTR + np * 16));
                uint32_t b0[2] = {r0, r1}, b1r[2] = {r2, r3};
                mma_f16(acc[0][np * 2],     a[0], b0);
                mma_f16(acc[1][np * 2],     a[1], b0);
                mma_f16(acc[0][np * 2 + 1], a[0], b1r);
                mma_f16(acc[1][np * 2 + 1], a[1], b1r);
            }
        }
        __syncthreads();
    }

    #pragma unroll
    for (int mt = 0; mt < 2; ++mt) {
        #pragma unroll
        for (int nt = 0; nt < 4; ++nt) {
            const int col = wn * 32 + nt * 8 + tg * 2;
            const float bb0 = b2[col], bb1 = b2[col + 1];
            #pragma unroll
            for (int h = 0; h < 2; ++h) {
                const int row = m0 + wm * 32 + mt * 16 + g + h * 8;
                float v0 = acc[mt][nt][h * 2 + 0] + bb0 + res[(size_t)row * 128 + col];
                float v1 = acc[mt][nt][h * 2 + 1] + bb1 + res[(size_t)row * 128 + col + 1];
                out[(size_t)row * 128 + col]     = v0;
                out[(size_t)row * 128 + col + 1] = v1;
            }
        }
    }
}

// ---------------- launch ----------------
extern "C" void kernel_launch(void* const* d_in, const int* in_sizes, int n_in,
                              void* d_out, int out_size) {
    const float* x     = (const float*)d_in[0];
    const float* dis   = (const float*)d_in[1];
    const float* g_in  = (const float*)d_in[2];
    const float* g_po  = (const float*)d_in[3];
    const float* Wq    = (const float*)d_in[4];
    const float* Wk    = (const float*)d_in[5];
    const float* Wv    = (const float*)d_in[6];
    const float* alpha = (const float*)d_in[7];
    const float* Wo    = (const float*)d_in[8];
    const float* W1    = (const float*)d_in[9];
    const float* b1    = (const float*)d_in[10];
    const float* W2    = (const float*)d_in[11];
    const float* b2    = (const float*)d_in[12];
    float* out = (float*)d_out;

    float* p_out1;
    cudaGetSymbolAddress((void**)&p_out1, g_out1);

    cudaFuncSetAttribute(big_kernel,
                         cudaFuncAttributeMaxDynamicSharedMemorySize, BIG_SMEM);
    cudaFuncSetAttribute(qkv_kernel,
                         cudaFuncAttributeMaxDynamicSharedMemorySize, QKV_SMEM);
    cudaFuncSetAttribute(wo_norm_kernel,
                         cudaFuncAttributeMaxDynamicSharedMemorySize, WO_SMEM);
    cudaFuncSetAttribute(ff1_kernel,
                         cudaFuncAttributeMaxDynamicSharedMemorySize, F1_SMEM);
    cudaFuncSetAttribute(ff2_kernel,
                         cudaFuncAttributeMaxDynamicSharedMemorySize, F2_SMEM);

    prep_kernel<<<2304, 256>>>(x, g_in, W1, W2, Wo, Wq, Wk, Wv);
    qkv_kernel<<<dim3(NTOK / 128, 4), 256, QKV_SMEM>>>();
    big_kernel<<<dim3(NSEQ / 64, NB), 256, BIG_SMEM>>>(dis, alpha);
    wo_norm_kernel<<<NTOK / 64, 256, WO_SMEM>>>(x, g_po, p_out1);
    ff1_kernel<<<dim3(NTOK / 128, 8), 256, F1_SMEM>>>(b1);
    ff2_kernel<<<NTOK / 64, 256, F2_SMEM>>>(b2, p_out1, out);
}

// round 17
// speedup vs baseline: 1.0203x; 1.0203x over previous
#include <cuda_runtime.h>
#include <cuda_fp16.h>
#include <cstdint>
#include <cstddef>

#define NB     4
#define NSEQ   4096
#define EDIM   128
#define FFD    512
#define NTOK   (NB * NSEQ)

// ---------------- scratch ----------------
__device__ __half g_hh  [NTOK * EDIM];
__device__ float  g_S   [NTOK * EDIM];
__device__ __half g_Xh  [NTOK * 256];
__device__ __half g_atth[NTOK * EDIM];
__device__ float  g_out1[NTOK * EDIM];
__device__ __half g_h2h [NTOK * EDIM];
__device__ __half g_W1h [EDIM * FFD];
__device__ __half g_W2h [FFD * EDIM];
__device__ __half g_Woh [EDIM * EDIM];
__device__ __half g_Wqh [EDIM * EDIM];
__device__ __half g_Wkh [EDIM * EDIM];
__device__ __half g_Wvh [EDIM * EDIM];

// ---------------- helpers ----------------
__device__ __forceinline__ void mma_f16(float* c, const uint32_t* a, const uint32_t* b) {
    asm volatile(
        "mma.sync.aligned.m16n8k16.row.col.f32.f16.f16.f32 "
        "{%0,%1,%2,%3}, {%4,%5,%6,%7}, {%8,%9}, {%0,%1,%2,%3};\n"
        : "+f"(c[0]), "+f"(c[1]), "+f"(c[2]), "+f"(c[3])
        : "r"(a[0]), "r"(a[1]), "r"(a[2]), "r"(a[3]), "r"(b[0]), "r"(b[1]));
}
__device__ __forceinline__ void cp16(void* s, const void* gp) {
    uint32_t sa = (uint32_t)__cvta_generic_to_shared(s);
    asm volatile("cp.async.cg.shared.global [%0], [%1], 16;\n" :: "r"(sa), "l"(gp));
}
__device__ __forceinline__ void cp_commit() {
    asm volatile("cp.async.commit_group;\n" ::: "memory");
}
__device__ __forceinline__ void cp_wait0() {
    asm volatile("cp.async.wait_group 0;\n" ::: "memory");
}
__device__ __forceinline__ void cp_wait1() {
    asm volatile("cp.async.wait_group 1;\n" ::: "memory");
}
__device__ __forceinline__ void ldmx4(uint32_t& r0, uint32_t& r1, uint32_t& r2,
                                      uint32_t& r3, uint32_t addr) {
    asm volatile("ldmatrix.sync.aligned.m8n8.x4.shared.b16 {%0,%1,%2,%3}, [%4];"
                 : "=r"(r0), "=r"(r1), "=r"(r2), "=r"(r3) : "r"(addr));
}
__device__ __forceinline__ void ldmx4t(uint32_t& r0, uint32_t& r1, uint32_t& r2,
                                       uint32_t& r3, uint32_t addr) {
    asm volatile("ldmatrix.sync.aligned.m8n8.x4.trans.shared.b16 {%0,%1,%2,%3}, [%4];"
                 : "=r"(r0), "=r"(r1), "=r"(r2), "=r"(r3) : "r"(addr));
}
__device__ __forceinline__ uint32_t smem_u32(const void* p) {
    return (uint32_t)__cvta_generic_to_shared(p);
}

// ---------------------------------------------------------------------------
// Prep: blocks [0, 2048): rmsnorm(x) -> g_hh (half);
//       blocks [2048, 2304): pack weights to half
// ---------------------------------------------------------------------------
__global__ void prep_kernel(const float* __restrict__ x,
                            const float* __restrict__ gw,
                            const float* __restrict__ W1,
                            const float* __restrict__ W2,
                            const float* __restrict__ Wo,
                            const float* __restrict__ Wq,
                            const float* __restrict__ Wk,
                            const float* __restrict__ Wv) {
    if (blockIdx.x < 2048) {
        int warp = (blockIdx.x * blockDim.x + threadIdx.x) >> 5;
        int lane = threadIdx.x & 31;
        float4 v = reinterpret_cast<const float4*>(x + (size_t)warp * EDIM)[lane];
        float ss = v.x * v.x + v.y * v.y + v.z * v.z + v.w * v.w;
        #pragma unroll
        for (int o = 16; o > 0; o >>= 1) ss += __shfl_xor_sync(0xffffffffu, ss, o);
        float s = rsqrtf(ss * (1.0f / 128.0f) + 1e-6f);
        float4 g4 = reinterpret_cast<const float4*>(gw)[lane];
        __half2 h0 = __floats2half2_rn(v.x * s * g4.x, v.y * s * g4.y);
        __half2 h1 = __floats2half2_rn(v.z * s * g4.z, v.w * s * g4.w);
        uint2 u;
        u.x = *reinterpret_cast<uint32_t*>(&h0);
        u.y = *reinterpret_cast<uint32_t*>(&h1);
        *reinterpret_cast<uint2*>(g_hh + (size_t)warp * EDIM + lane * 4) = u;
    } else {
        int i = (blockIdx.x - 2048) * blockDim.x + threadIdx.x;
        g_W1h[i] = __float2half(W1[i]);
        g_W2h[i] = __float2half(W2[i]);
        if (i < EDIM * EDIM) {
            g_Woh[i] = __float2half(Wo[i]);
            g_Wqh[i] = __float2half(Wq[i]);
            g_Wkh[i] = __float2half(Wk[i]);
            g_Wvh[i] = __float2half(Wv[i]);
        }
    }
}

// ---------------------------------------------------------------------------
// QKV (fp16, K=128 resident, one sync) — R15 verbatim
// ---------------------------------------------------------------------------
#define Q2_ASTR 136
#define Q2_BOFF 17408
#define Q2_BSTR 40
#define Q2_BBUF 5120
#define QKV_SMEM ((Q2_BOFF + 3 * Q2_BBUF) * 2)

__global__ __launch_bounds__(256)
void qkv_kernel() {
    extern __shared__ __half smq[];
    __half* Ah = smq;
    __half* Bh = smq + Q2_BOFF;
    const uint32_t smb = smem_u32(smq);

    const int m0 = blockIdx.x * 128;
    const int j0 = blockIdx.y * 32;
    const int tid = threadIdx.x, lane = tid & 31, warp = tid >> 5;
    const int wm = warp >> 1, wn = warp & 1;
    const int g = lane >> 2, tg = lane & 3;
    const int lr = lane & 7, sel = lane >> 3;

    const __half* Wh[3] = {g_Wqh, g_Wkh, g_Wvh};

    #pragma unroll
    for (int i = 0; i < 8; i++) {
        int id = tid + i * 256;
        int m = id >> 4, c = (id & 15) << 3;
        cp16(Ah + m * Q2_ASTR + c, g_hh + (size_t)(m0 + m) * 128 + c);
    }
    #pragma unroll
    for (int w = 0; w < 3; w++) {
        #pragma unroll
        for (int i = 0; i < 2; i++) {
            int id = tid + i * 256;
            int k = id >> 2, c = (id & 3) << 3;
            cp16(Bh + w * Q2_BBUF + k * Q2_BSTR + c,
                 Wh[w] + (size_t)k * 128 + j0 + c);
        }
    }
    cp_commit();
    cp_wait0();
    __syncthreads();

    uint32_t aoff[2];
    #pragma unroll
    for (int mt = 0; mt < 2; ++mt)
        aoff[mt] = (uint32_t)((wm * 32 + mt * 16 + (sel & 1) * 8 + lr) * Q2_ASTR +
                              (sel >> 1) * 8);
    const uint32_t lmB = (uint32_t)((lane & 15) * Q2_BSTR + wn * 16 + ((lane >> 4) << 3));

    float acc[3][2][2][4];
    #pragma unroll
    for (int w = 0; w < 3; w++)
        #pragma unroll
        for (int i = 0; i < 2; i++)
            #pragma unroll
            for (int j = 0; j < 2; j++)
                #pragma unroll
                for (int r = 0; r < 4; r++) acc[w][i][j][r] = 0.0f;

    #pragma unroll
    for (int kb = 0; kb < 128; kb += 16) {
        uint32_t a[2][4];
        #pragma unroll
        for (int mt = 0; mt < 2; ++mt)
            ldmx4(a[mt][0], a[mt][1], a[mt][2], a[mt][3],
                  smb + 2u * (aoff[mt] + kb));
        #pragma unroll
        for (int w = 0; w < 3; w++) {
            uint32_t r0, r1, r2, r3;
            ldmx4t(r0, r1, r2, r3,
                   smb + 2u * (Q2_BOFF + w * Q2_BBUF + lmB + kb * Q2_BSTR));
            uint32_t b0[2] = {r0, r1}, b1[2] = {r2, r3};
            mma_f16(acc[w][0][0], a[0], b0);
            mma_f16(acc[w][1][0], a[1], b0);
            mma_f16(acc[w][0][1], a[0], b1);
            mma_f16(acc[w][1][1], a[1], b1);
        }
    }

    #pragma unroll
    for (int mt = 0; mt < 2; ++mt) {
        #pragma unroll
        for (int nt = 0; nt < 2; ++nt) {
            const int col = j0 + wn * 16 + nt * 8 + tg * 2;
            #pragma unroll
            for (int hh = 0; hh < 2; ++hh) {
                const int row = m0 + wm * 32 + mt * 16 + g + hh * 8;
                float q0 = acc[0][mt][nt][hh * 2], q1 = acc[0][mt][nt][hh * 2 + 1];
                float k0v = acc[1][mt][nt][hh * 2], k1v = acc[1][mt][nt][hh * 2 + 1];
                float v0 = acc[2][mt][nt][hh * 2], v1 = acc[2][mt][nt][hh * 2 + 1];
                float2 s2 = make_float2(1.0f / (1.0f + expf(-q0)),
                                        1.0f / (1.0f + expf(-q1)));
                *reinterpret_cast<float2*>(g_S + (size_t)row * 128 + col) = s2;
                float kw0 = expf(k0v), kw1 = expf(k1v);
                __half2 h0 = __floats2half2_rn(kw0 * v0, kw0);
                __half2 h1 = __floats2half2_rn(kw1 * v1, kw1);
                uint2 u;
                u.x = *reinterpret_cast<uint32_t*>(&h0);
                u.y = *reinterpret_cast<uint32_t*>(&h1);
                *reinterpret_cast<uint2*>(g_Xh + (size_t)row * 256 + 2 * col) = u;
            }
        }
    }
}

// ---------------------------------------------------------------------------
// Big GEMM (fp16 m16n8k16) — R10/R15 structure verbatim (127 µs; FROZEN)
// ---------------------------------------------------------------------------
#define AH_STR 40
#define AH_BUF 5120
#define BH_STR 264
#define BH_BUF 8448
#define BH_OFF 10240
#define BIG_SMEM 71168

__global__ __launch_bounds__(512, 1)
void big_kernel(const float* __restrict__ dis, const float* __restrict__ alphap) {
    extern __shared__ __half smh[];
    __half* Ah = smh;
    __half* Bh = smh + BH_OFF;
    const uint32_t smb = smem_u32(smh);

    const int tid = threadIdx.x, lane = tid & 31, warp = tid >> 5;
    const int wm = warp >> 2, wn = warp & 3;
    const int g = lane >> 2, tg = lane & 3;
    const int b = blockIdx.y, j0 = blockIdx.x * 128;
    const float coef = 12.0f * alphap[0];
    const float* Ag = dis + (size_t)b * NSEQ * NSEQ;
    const __half* Xg = g_Xh + (size_t)b * NSEQ * 256;

    const int am = tid & 127, ar4 = (tid >> 7) << 2;

    const int lr = lane & 7, sel = lane >> 3;
    uint32_t aoff[2];
    #pragma unroll
    for (int mt = 0; mt < 2; ++mt)
        aoff[mt] = (uint32_t)((wm * 32 + mt * 16 + (sel & 1) * 8 + lr) * AH_STR +
                              (sel >> 1) * 8);
    const uint32_t lm_half = (uint32_t)((lane & 15) * BH_STR + wn * 64 + ((lane >> 4) << 3));

    float ra[2][4];
    float acc[2][8][4];
    #pragma unroll
    for (int i = 0; i < 2; i++)
        #pragma unroll
        for (int j = 0; j < 8; j++)
            #pragma unroll
            for (int r = 0; r < 4; r++) acc[i][j][r] = 0.0f;

    auto ldA = [&](int k0) {
        #pragma unroll
        for (int it = 0; it < 2; ++it) {
            const float* p = Ag + (size_t)(k0 + it * 16 + ar4) * NSEQ + j0 + am;
            ra[it][0] = p[0]; ra[it][1] = p[NSEQ];
            ra[it][2] = p[2 * NSEQ]; ra[it][3] = p[3 * NSEQ];
        }
    };
    auto stA = [&](int buf) {
        __half* base = Ah + buf * AH_BUF + am * AH_STR;
        #pragma unroll
        for (int it = 0; it < 2; ++it) {
            __half2 h01 = __floats2half2_rn(__expf(-coef * ra[it][0]),
                                            __expf(-coef * ra[it][1]));
            __half2 h23 = __floats2half2_rn(__expf(-coef * ra[it][2]),
                                            __expf(-coef * ra[it][3]));
            uint2 u;
            u.x = *reinterpret_cast<uint32_t*>(&h01);
            u.y = *reinterpret_cast<uint32_t*>(&h23);
            *reinterpret_cast<uint2*>(base + it * 16 + ar4) = u;
        }
    };
    auto cpB = [&](int stage, int k0) {
        #pragma unroll
        for (int it = 0; it < 2; ++it) {
            int ch = tid + it * 512;
            int row = ch >> 5, cc = (ch & 31) << 3;
            cp16(Bh + stage * BH_BUF + row * BH_STR + cc,
                 Xg + (size_t)(k0 + row) * 256 + cc);
        }
    };

    cpB(0, 0);  cp_commit();
    cpB(1, 32); cp_commit();
    ldA(0);
    stA(0);
    cp_wait1();
    __syncthreads();

    for (int kt = 0; kt < 128; ++kt) {
        const int sbuf = kt % 3;
        const int abuf = kt & 1;
        if (kt + 2 < 128) { cpB((kt + 2) % 3, (kt + 2) * 32); cp_commit(); }
        if (kt + 1 < 128) ldA((kt + 1) * 32);

        const uint32_t abase = smb + 2u * (abuf * AH_BUF);
        const uint32_t bbase = smb + 2u * (BH_OFF + sbuf * BH_BUF + lm_half);
        #pragma unroll
        for (int ks = 0; ks < 2; ++ks) {
            const int kb = ks * 16;
            uint32_t a[2][4];
            #pragma unroll
            for (int mt = 0; mt < 2; ++mt)
                ldmx4(a[mt][0], a[mt][1], a[mt][2], a[mt][3],
                      abase + 2u * (aoff[mt] + kb));
            #pragma unroll
            for (int np = 0; np < 4; ++np) {
                uint32_t r0, r1, r2, r3;
                ldmx4t(r0, r1, r2, r3, bbase + 2u * (kb * BH_STR + np * 16));
                uint32_t b0[2] = {r0, r1}, b1[2] = {r2, r3};
                mma_f16(acc[0][np * 2],     a[0], b0);
                mma_f16(acc[1][np * 2],     a[1], b0);
                mma_f16(acc[0][np * 2 + 1], a[0], b1);
                mma_f16(acc[1][np * 2 + 1], a[1], b1);
            }
        }
        if (kt + 1 < 128) stA(abuf ^ 1);
        cp_wait1();
        __syncthreads();
    }

    const size_t rowbase = (size_t)b * NSEQ + j0;
    #pragma unroll
    for (int mt = 0; mt < 2; ++mt) {
        const int r0 = wm * 32 + mt * 16 + g;
        #pragma unroll
        for (int nt = 0; nt < 8; ++nt) {
            const int e = wn * 32 + nt * 4 + tg;
            const size_t i0 = (rowbase + r0) * 128 + e;
            const size_t i1 = (rowbase + r0 + 8) * 128 + e;
            float a0 = g_S[i0] * __fdividef(acc[mt][nt][0], acc[mt][nt][1]);
            float a1 = g_S[i1] * __fdividef(acc[mt][nt][2], acc[mt][nt][3]);
            g_atth[i0] = __float2half(a0);
            g_atth[i1] = __float2half(a1);
        }
    }
}

// ---------------------------------------------------------------------------
// Wo (fp16 resident) + residual + fused post-rmsnorm. BM=64 — R15 verbatim
// ---------------------------------------------------------------------------
#define WO_STR 136
#define WO_BOFF 8704
#define WO_SMEM ((WO_BOFF + 128 * WO_STR) * 2)

__global__ __launch_bounds__(256)
void wo_norm_kernel(const float* __restrict__ x, const float* __restrict__ gpost,
                    float* __restrict__ out1) {
    extern __shared__ __half smw[];
    __shared__ float rowss[64];
    __half* Ah = smw;
    __half* Bh = smw + WO_BOFF;
    const uint32_t smb = smem_u32(smw);

    const int m0 = blockIdx.x * 64;
    const int tid = threadIdx.x, lane = tid & 31, warp = tid >> 5;
    const int wm = warp >> 2, wn = warp & 3;
    const int g = lane >> 2, tg = lane & 3;
    const int lr = lane & 7, sel = lane >> 3;

    #pragma unroll
    for (int i = 0; i < 4; i++) {
        int id = tid + i * 256;
        int m = id >> 4, c = (id & 15) << 3;
        cp16(Ah + m * WO_STR + c, g_atth + (size_t)(m0 + m) * 128 + c);
    }
    #pragma unroll
    for (int i = 0; i < 8; i++) {
        int id = tid + i * 256;
        int m = id >> 4, c = (id & 15) << 3;
        cp16(Bh + m * WO_STR + c, g_Woh + (size_t)m * 128 + c);
    }
    cp_commit();
    if (tid < 64) rowss[tid] = 0.0f;
    cp_wait0();
    __syncthreads();

    uint32_t aoff[2];
    #pragma unroll
    for (int mt = 0; mt < 2; ++mt)
        aoff[mt] = (uint32_t)((wm * 32 + mt * 16 + (sel & 1) * 8 + lr) * WO_STR +
                              (sel >> 1) * 8);
    const uint32_t lm = (uint32_t)((lane & 15) * WO_STR + wn * 32 + ((lane >> 4) << 3));

    float acc[2][4][4];
    #pragma unroll
    for (int i = 0; i < 2; i++)
        #pragma unroll
        for (int j = 0; j < 4; j++)
            #pragma unroll
            for (int r = 0; r < 4; r++) acc[i][j][r] = 0.0f;

    #pragma unroll
    for (int kb = 0; kb < 128; kb += 16) {
        uint32_t a[2][4];
        #pragma unroll
        for (int mt = 0; mt < 2; ++mt)
            ldmx4(a[mt][0], a[mt][1], a[mt][2], a[mt][3],
                  smb + 2u * (aoff[mt] + kb));
        #pragma unroll
        for (int np = 0; np < 2; ++np) {
            uint32_t r0, r1, r2, r3;
            ldmx4t(r0, r1, r2, r3,
                   smb + 2u * (WO_BOFF + lm + kb * WO_STR + np * 16));
            uint32_t b0[2] = {r0, r1}, b1r[2] = {r2, r3};
            mma_f16(acc[0][np * 2],     a[0], b0);
            mma_f16(acc[1][np * 2],     a[1], b0);
            mma_f16(acc[0][np * 2 + 1], a[0], b1r);
            mma_f16(acc[1][np * 2 + 1], a[1], b1r);
        }
    }

    #pragma unroll
    for (int mt = 0; mt < 2; ++mt) {
        #pragma unroll
        for (int h = 0; h < 2; ++h) {
            const int rl = wm * 32 + mt * 16 + g + h * 8;
            const size_t rowg = (size_t)(m0 + rl);
            float ss = 0.0f;
            #pragma unroll
            for (int nt = 0; nt < 4; ++nt) {
                const int c = wn * 32 + nt * 8 + tg * 2;
                float2 xv = *reinterpret_cast<const float2*>(x + rowg * 128 + c);
                float v0 = acc[mt][nt][h * 2 + 0] + xv.x;
                float v1 = acc[mt][nt][h * 2 + 1] + xv.y;
                acc[mt][nt][h * 2 + 0] = v0;
                acc[mt][nt][h * 2 + 1] = v1;
                *reinterpret_cast<float2*>(out1 + rowg * 128 + c) = make_float2(v0, v1);
                ss += v0 * v0 + v1 * v1;
            }
            ss += __shfl_xor_sync(0xffffffffu, ss, 1);
            ss += __shfl_xor_sync(0xffffffffu, ss, 2);
            if (tg == 0) atomicAdd(&rowss[rl], ss);
        }
    }
    __syncthreads();

    #pragma unroll
    for (int mt = 0; mt < 2; ++mt) {
        #pragma unroll
        for (int h = 0; h < 2; ++h) {
            const int rl = wm * 32 + mt * 16 + g + h * 8;
            const size_t rowg = (size_t)(m0 + rl);
            const float sc = rsqrtf(rowss[rl] * (1.0f / 128.0f) + 1e-6f);
            #pragma unroll
            for (int nt = 0; nt < 4; ++nt) {
                const int c = wn * 32 + nt * 8 + tg * 2;
                float2 gp = *reinterpret_cast<const float2*>(gpost + c);
                __half2 hv = __floats2half2_rn(acc[mt][nt][h * 2 + 0] * sc * gp.x,
                                               acc[mt][nt][h * 2 + 1] * sc * gp.y);
                *reinterpret_cast<uint32_t*>(g_h2h + rowg * 128 + c) =
                    *reinterpret_cast<uint32_t*>(&hv);
            }
        }
    }
}

// ---------------------------------------------------------------------------
// FF fused (fp16): t = relu(h2@W1+b1) kept in smem; out = out1 + t@W2 + b2.
// BM=64 tokens, grid 256, 8 warps (2m x 4n, warp tile 32m x 32n).
// W1 streamed in 4 x 128-col chunks; W2 in 4 x 128-row chunks (double-buffered
// through the same window, ff2's proven sync pattern).
// smem (halfs): h2 [64][136] @0 ; Ts [64][520] @8704 ; Wbuf 2x[128][136] @41984
// ---------------------------------------------------------------------------
#define FF_ASTR 136
#define FF_TOFF 8704
#define FF_TSTR 520
#define FF_WOFF 41984
#define FF_WBUF 17408
#define FF_SMEM ((FF_WOFF + 2 * FF_WBUF) * 2)   // 153600 bytes

__global__ __launch_bounds__(256)
void ff_fused_kernel(const float* __restrict__ b1, const float* __restrict__ b2,
                     const float* __restrict__ res, float* __restrict__ out) {
    extern __shared__ __half smf[];
    const uint32_t smb = smem_u32(smf);

    const int m0 = blockIdx.x * 64;
    const int tid = threadIdx.x, lane = tid & 31, warp = tid >> 5;
    const int wm = warp >> 2, wn = warp & 3;   // 2m x 4n
    const int g = lane >> 2, tg = lane & 3;
    const int lr = lane & 7, sel = lane >> 3;

    auto cpW1 = [&](int buf, int nc) {
        __half* W = smf + FF_WOFF + buf * FF_WBUF;
        #pragma unroll
        for (int i = 0; i < 8; i++) {
            int id = tid + i * 256;
            int k = id >> 4, c = (id & 15) << 3;
            cp16(W + k * FF_ASTR + c, g_W1h + (size_t)k * FFD + nc * 128 + c);
        }
    };
    auto cpW2 = [&](int buf, int kc) {
        __half* W = smf + FF_WOFF + buf * FF_WBUF;
        #pragma unroll
        for (int i = 0; i < 8; i++) {
            int id = tid + i * 256;
            int k = id >> 4, c = (id & 15) << 3;
            cp16(W + k * FF_ASTR + c, g_W2h + (size_t)(kc * 128 + k) * EDIM + c);
        }
    };

    // load h2 tile (64x128) + W1 chunk 0 — one group
    #pragma unroll
    for (int i = 0; i < 4; i++) {
        int id = tid + i * 256;
        int m = id >> 4, c = (id & 15) << 3;
        cp16(smf + m * FF_ASTR + c, g_h2h + (size_t)(m0 + m) * 128 + c);
    }
    cpW1(0, 0);
    cp_commit();

    uint32_t aoff1[2], aoff2[2];
    #pragma unroll
    for (int mt = 0; mt < 2; ++mt) {
        const int row = wm * 32 + mt * 16 + (sel & 1) * 8 + lr;
        aoff1[mt] = (uint32_t)(row * FF_ASTR + (sel >> 1) * 8);
        aoff2[mt] = (uint32_t)(FF_TOFF + row * FF_TSTR + (sel >> 1) * 8);
    }
    const uint32_t lmW = (uint32_t)((lane & 15) * FF_ASTR + wn * 32 + ((lane >> 4) << 3));

    // ---------------- Phase 1: FF1, t -> smem ----------------
    for (int nc = 0; nc < 4; ++nc) {
        const int buf = nc & 1;
        if (nc + 1 < 4) { cpW1(buf ^ 1, nc + 1); cp_commit(); cp_wait1(); }
        else            { cp_wait0(); }
        __syncthreads();

        float acc[2][4][4];
        #pragma unroll
        for (int i = 0; i < 2; i++)
            #pragma unroll
            for (int j = 0; j < 4; j++)
                #pragma unroll
                for (int r = 0; r < 4; r++) acc[i][j][r] = 0.0f;

        const uint32_t bbase = smb + 2u * (FF_WOFF + buf * FF_WBUF + lmW);
        #pragma unroll
        for (int kb = 0; kb < 128; kb += 16) {
            uint32_t a[2][4];
            #pragma unroll
            for (int mt = 0; mt < 2; ++mt)
                ldmx4(a[mt][0], a[mt][1], a[mt][2], a[mt][3],
                      smb + 2u * (aoff1[mt] + kb));
            #pragma unroll
            for (int np = 0; np < 2; ++np) {
                uint32_t r0, r1, r2, r3;
                ldmx4t(r0, r1, r2, r3, bbase + 2u * (kb * FF_ASTR + np * 16));
                uint32_t b0[2] = {r0, r1}, b1r[2] = {r2, r3};
                mma_f16(acc[0][np * 2],     a[0], b0);
                mma_f16(acc[1][np * 2],     a[1], b0);
                mma_f16(acc[0][np * 2 + 1], a[0], b1r);
                mma_f16(acc[1][np * 2 + 1], a[1], b1r);
            }
        }

        // relu(+b1) -> Ts
        #pragma unroll
        for (int mt = 0; mt < 2; ++mt) {
            #pragma unroll
            for (int nt = 0; nt < 4; ++nt) {
                const int col = wn * 32 + nt * 8 + tg * 2;
                const int gcol = nc * 128 + col;
                const float bb0 = b1[gcol], bb1 = b1[gcol + 1];
                #pragma unroll
                for (int h = 0; h < 2; ++h) {
                    const int row = wm * 32 + mt * 16 + g + h * 8;
                    float v0 = fmaxf(acc[mt][nt][h * 2 + 0] + bb0, 0.0f);
                    float v1 = fmaxf(acc[mt][nt][h * 2 + 1] + bb1, 0.0f);
                    __half2 hv = __floats2half2_rn(v0, v1);
                    *reinterpret_cast<uint32_t*>(smf + FF_TOFF + row * FF_TSTR + gcol) =
                        *reinterpret_cast<uint32_t*>(&hv);
                }
            }
        }
        __syncthreads();
    }

    // ---------------- Phase 2: FF2 from smem t ----------------
    cpW2(0, 0);
    cp_commit();

    float acc[2][4][4];
    #pragma unroll
    for (int i = 0; i < 2; i++)
        #pragma unroll
        for (int j = 0; j < 4; j++)
            #pragma unroll
            for (int r = 0; r < 4; r++) acc[i][j][r] = 0.0f;

    for (int kc = 0; kc < 4; ++kc) {
        const int buf = kc & 1;
        if (kc + 1 < 4) { cpW2(buf ^ 1, kc + 1); cp_commit(); cp_wait1(); }
        else            { cp_wait0(); }
        __syncthreads();

        const uint32_t bbase = smb + 2u * (FF_WOFF + buf * FF_WBUF + lmW);
        #pragma unroll
        for (int kb = 0; kb < 128; kb += 16) {
            uint32_t a[2][4];
            #pragma unroll
            for (int mt = 0; mt < 2; ++mt)
                ldmx4(a[mt][0], a[mt][1], a[mt][2], a[mt][3],
                      smb + 2u * (aoff2[mt] + kc * 128 + kb));
            #pragma unroll
            for (int np = 0; np < 2; ++np) {
                uint32_t r0, r1, r2, r3;
                ldmx4t(r0, r1, r2, r3, bbase + 2u * (kb * FF_ASTR + np * 16));
                uint32_t b0[2] = {r0, r1}, b1r[2] = {r2, r3};
                mma_f16(acc[0][np * 2],     a[0], b0);
                mma_f16(acc[1][np * 2],     a[1], b0);
                mma_f16(acc[0][np * 2 + 1], a[0], b1r);
                mma_f16(acc[1][np * 2 + 1], a[1], b1r);
            }
        }
        __syncthreads();
    }

    // epilogue: out = acc + b2 + out1
    #pragma unroll
    for (int mt = 0; mt < 2; ++mt) {
        #pragma unroll
        for (int nt = 0; nt < 4; ++nt) {
            const int col = wn * 32 + nt * 8 + tg * 2;
            const float bb0 = b2[col], bb1 = b2[col + 1];
            #pragma unroll
            for (int h = 0; h < 2; ++h) {
                const int row = m0 + wm * 32 + mt * 16 + g + h * 8;
                float v0 = acc[mt][nt][h * 2 + 0] + bb0 + res[(size_t)row * 128 + col];
                float v1 = acc[mt][nt][h * 2 + 1] + bb1 + res[(size_t)row * 128 + col + 1];
                out[(size_t)row * 128 + col]     = v0;
                out[(size_t)row * 128 + col + 1] = v1;
            }
        }
    }
}

// ---------------- launch ----------------
extern "C" void kernel_launch(void* const* d_in, const int* in_sizes, int n_in,
                              void* d_out, int out_size) {
    const float* x     = (const float*)d_in[0];
    const float* dis   = (const float*)d_in[1];
    const float* g_in  = (const float*)d_in[2];
    const float* g_po  = (const float*)d_in[3];
    const float* Wq    = (const float*)d_in[4];
    const float* Wk    = (const float*)d_in[5];
    const float* Wv    = (const float*)d_in[6];
    const float* alpha = (const float*)d_in[7];
    const float* Wo    = (const float*)d_in[8];
    const float* W1    = (const float*)d_in[9];
    const float* b1    = (const float*)d_in[10];
    const float* W2    = (const float*)d_in[11];
    const float* b2    = (const float*)d_in[12];
    float* out = (float*)d_out;

    float* p_out1;
    cudaGetSymbolAddress((void**)&p_out1, g_out1);

    cudaFuncSetAttribute(big_kernel,
                         cudaFuncAttributeMaxDynamicSharedMemorySize, BIG_SMEM);
    cudaFuncSetAttribute(qkv_kernel,
                         cudaFuncAttributeMaxDynamicSharedMemorySize, QKV_SMEM);
    cudaFuncSetAttribute(wo_norm_kernel,
                         cudaFuncAttributeMaxDynamicSharedMemorySize, WO_SMEM);
    cudaFuncSetAttribute(ff_fused_kernel,
                         cudaFuncAttributeMaxDynamicSharedMemorySize, FF_SMEM);

    prep_kernel<<<2304, 256>>>(x, g_in, W1, W2, Wo, Wq, Wk, Wv);
    qkv_kernel<<<dim3(NTOK / 128, 4), 256, QKV_SMEM>>>();
    big_kernel<<<dim3(NSEQ / 128, NB), 512, BIG_SMEM>>>(dis, alpha);
    wo_norm_kernel<<<NTOK / 64, 256, WO_SMEM>>>(x, g_po, p_out1);
    ff_fused_kernel<<<NTOK / 64, 256, FF_SMEM>>>(b1, b2, p_out1, out);
}